// round 7
// baseline (speedup 1.0000x reference)
#include <cuda_runtime.h>

#define H_DIM 512
#define W_DIM 512
#define RPB   8       // output rows per block
#define NTHREADS 128  // 4 px/thread * 128 threads = 512 columns = full row
#define MAX_BLOCKS 8192

__device__ float    g_part[MAX_BLOCKS];
__device__ unsigned g_ticket;   // zero-init; restored to 0 by last block each run

// Per-row separable Sobel pieces for 4 consecutive pixels:
//   d[j] = val(x-1) - val(x+1)            (horizontal part of SOBEL_X)
//   s[j] = val(x-1) + 2*val(x) + val(x+1) (horizontal part of SOBEL_Y)
struct DS { float dx, dy, dz, dw, sx, sy, sz, sw; };

__device__ __forceinline__ DS row_ds(const float* __restrict__ row,
                                     int x0, int xm, int xp) {
    float4 v  = *reinterpret_cast<const float4*>(row + x0);
    float xm1 = __ldg(row + xm);
    float xp4 = __ldg(row + xp);
    DS r;
    r.dx = xm1 - v.y;  r.dy = v.x - v.z;  r.dz = v.y - v.w;  r.dw = v.z - xp4;
    r.sx = fmaf(2.f, v.x, xm1) + v.y;
    r.sy = fmaf(2.f, v.y, v.x) + v.z;
    r.sz = fmaf(2.f, v.z, v.y) + v.w;
    r.sw = fmaf(2.f, v.w, v.z) + xp4;
    return r;
}

// Minimal normal math:
//   q = gx^2+gy^2 ;  length^2 = (2gx)^2+(2gy)^2+gz^2 = 0.0625 + 3.9375 q = v
//   w = rsqrt(v) = 1/length  =>  nx = gx*w, ny = gy*w, 4*nz = sqrt(1-q)*w
//   sqrt(1-q) ~= 1 - q/2 - q^2/8  (err <= q^3/16 <= 3.2e-5 at q=0.08)
__device__ __forceinline__ void nrm(float gx, float gy,
                                    float& nx, float& ny, float& z4) {
    float q  = fmaf(gx, gx, gy * gy);
    float w  = rsqrtf(fmaf(3.9375f, q, 0.0625f));
    float su = fmaf(q, fmaf(q, -0.125f, -0.5f), 1.f);
    nx = gx * w;
    ny = gy * w;
    z4 = su * w;               // 4*nz ; 0.25 folded into final accumulation
}

// Accumulates |dnx|+|dny| into axy and |d(4nz)| into az.
__device__ __forceinline__ void contrib(
    float dpg, float dcg, float dng, float spg, float sng,
    float dpt, float dct, float dnt, float spt, float snt,
    float& axy, float& az) {
    float gxg = fmaf(2.f, dcg, dpg) + dng;
    float gyg = spg - sng;
    float gxt = fmaf(2.f, dct, dpt) + dnt;
    float gyt = spt - snt;
    float nxg, nyg, zg, nxt, nyt, zt;
    nrm(gxg, gyg, nxg, nyg, zg);
    nrm(gxt, gyt, nxt, nyt, zt);
    axy += fabsf(nxg - nxt) + fabsf(nyg - nyt);
    az  += fabsf(zg - zt);
}

__global__ void __launch_bounds__(NTHREADS, 8)
heightmap_loss_kernel(const float* __restrict__ gen, const float* __restrict__ tgt,
                      float* __restrict__ out, double inv_n) {
    const int b    = blockIdx.y;
    const int y0   = blockIdx.x * RPB;
    const int lane = threadIdx.x & 31;
    const int x0   = threadIdx.x * 4;
    const int xm   = max(x0 - 1, 0);
    const int xp   = min(x0 + 4, W_DIM - 1);
    const int nblocks = gridDim.x * gridDim.y;
    const int bid     = blockIdx.y * gridDim.x + blockIdx.x;

    const float* __restrict__ gimg = gen + (size_t)b * (H_DIM * W_DIM);
    const float* __restrict__ timg = tgt + (size_t)b * (H_DIM * W_DIM);

    // rolling 3-row window (prev, cur, next) per image
    DS gP, gC, gN, tP, tC, tN;
    {
        int ym = max(y0 - 1, 0);
        gP = row_ds(gimg + ym * W_DIM, x0, xm, xp);
        tP = row_ds(timg + ym * W_DIM, x0, xm, xp);
        gC = row_ds(gimg + y0 * W_DIM, x0, xm, xp);
        tC = row_ds(timg + y0 * W_DIM, x0, xm, xp);
    }

    float axy = 0.f, az = 0.f;

    // Rows 0..RPB-2: y0+yy+1 <= y0+RPB-1 <= 511 always -> no clamp needed.
    #pragma unroll
    for (int yy = 0; yy < RPB - 1; yy++) {
        const float* grow = gimg + (y0 + yy + 1) * W_DIM;
        const float* trow = timg + (y0 + yy + 1) * W_DIM;
        gN = row_ds(grow, x0, xm, xp);
        tN = row_ds(trow, x0, xm, xp);

        contrib(gP.dx, gC.dx, gN.dx, gP.sx, gN.sx,
                tP.dx, tC.dx, tN.dx, tP.sx, tN.sx, axy, az);
        contrib(gP.dy, gC.dy, gN.dy, gP.sy, gN.sy,
                tP.dy, tC.dy, tN.dy, tP.sy, tN.sy, axy, az);
        contrib(gP.dz, gC.dz, gN.dz, gP.sz, gN.sz,
                tP.dz, tC.dz, tN.dz, tP.sz, tN.sz, axy, az);
        contrib(gP.dw, gC.dw, gN.dw, gP.sw, gN.sw,
                tP.dw, tC.dw, tN.dw, tP.sw, tN.sw, axy, az);

        gP = gC; gC = gN;
        tP = tC; tC = tN;
    }

    // Last row: clamp (active only for the bottom tile y0 = H-RPB).
    {
        int yn = min(y0 + RPB, H_DIM - 1);
        gN = row_ds(gimg + yn * W_DIM, x0, xm, xp);
        tN = row_ds(timg + yn * W_DIM, x0, xm, xp);

        contrib(gP.dx, gC.dx, gN.dx, gP.sx, gN.sx,
                tP.dx, tC.dx, tN.dx, tP.sx, tN.sx, axy, az);
        contrib(gP.dy, gC.dy, gN.dy, gP.sy, gN.sy,
                tP.dy, tC.dy, tN.dy, tP.sy, tN.sy, axy, az);
        contrib(gP.dz, gC.dz, gN.dz, gP.sz, gN.sz,
                tP.dz, tC.dz, tN.dz, tP.sz, tN.sz, axy, az);
        contrib(gP.dw, gC.dw, gN.dw, gP.sw, gN.sw,
                tP.dw, tC.dw, tN.dw, tP.sw, tN.sw, axy, az);
    }

    float acc = fmaf(0.25f, az, axy);

    // warp reduce
    #pragma unroll
    for (int o = 16; o > 0; o >>= 1)
        acc += __shfl_down_sync(0xffffffffu, acc, o);

    __shared__ float ws[NTHREADS / 32];
    __shared__ bool  isLast;
    if (lane == 0) ws[threadIdx.x >> 5] = acc;
    __syncthreads();
    if (threadIdx.x == 0) {
        g_part[bid] = ws[0] + ws[1] + ws[2] + ws[3];
        __threadfence();
        unsigned prev = atomicAdd(&g_ticket, 1u);
        isLast = (prev == (unsigned)(nblocks - 1));
    }
    __syncthreads();

    // Last block to finish performs the deterministic final reduction.
    if (isLast) {
        double s = 0.0;
        for (int i = threadIdx.x; i < nblocks; i += NTHREADS)
            s += (double)g_part[i];
        #pragma unroll
        for (int o = 16; o > 0; o >>= 1)
            s += __shfl_down_sync(0xffffffffu, s, o);
        __shared__ double ds[NTHREADS / 32];
        if (lane == 0) ds[threadIdx.x >> 5] = s;
        __syncthreads();
        if (threadIdx.x == 0) {
            double t = ds[0] + ds[1] + ds[2] + ds[3];
            out[0] = (float)(t * inv_n);
            g_ticket = 0u;   // restore invariant for graph replay
        }
    }
}

extern "C" void kernel_launch(void* const* d_in, const int* in_sizes, int n_in,
                              void* d_out, int out_size) {
    const float* gen = (const float*)d_in[0];
    const float* tgt = (const float*)d_in[1];
    float* out = (float*)d_out;

    const int total = in_sizes[0];              // B*1*H*W
    const int B = total / (H_DIM * W_DIM);

    dim3 grid(H_DIM / RPB, B);
    heightmap_loss_kernel<<<grid, NTHREADS>>>(gen, tgt, out,
                                              1.0 / (3.0 * (double)total));
}

// round 8
// speedup vs baseline: 1.1961x; 1.1961x over previous
#include <cuda_runtime.h>

#define H_DIM 512
#define W_DIM 512
#define RPB   8       // output rows per block
#define NTHREADS 128  // 4 px/thread * 128 threads = 512 columns = full row
#define MAX_BLOCKS 8192

__device__ float    g_part[MAX_BLOCKS];
__device__ unsigned g_ticket;   // zero-init; restored to 0 by last block each run

// Per-row separable Sobel pieces for 4 consecutive pixels:
//   d[j] = val(x-1) - val(x+1)            (horizontal part of SOBEL_X)
//   s[j] = val(x-1) + 2*val(x) + val(x+1) (horizontal part of SOBEL_Y)
struct DS { float dx, dy, dz, dw, sx, sy, sz, sw; };

// Halo via two clamped scalar LDGs (L1 hits) — no SHFL, no lane predicates.
__device__ __forceinline__ DS row_ds(const float* __restrict__ row,
                                     int x0, int xm, int xp) {
    float4 v  = *reinterpret_cast<const float4*>(row + x0);
    float xm1 = __ldg(row + xm);
    float xp4 = __ldg(row + xp);
    DS r;
    r.dx = xm1 - v.y;  r.dy = v.x - v.z;  r.dz = v.y - v.w;  r.dw = v.z - xp4;
    r.sx = fmaf(2.f, v.x, xm1) + v.y;
    r.sy = fmaf(2.f, v.y, v.x) + v.z;
    r.sz = fmaf(2.f, v.z, v.y) + v.w;
    r.sw = fmaf(2.f, v.w, v.z) + xp4;
    return r;
}

// Minimal normal math:
//   q = gx^2+gy^2 ;  length^2 = (2gx)^2+(2gy)^2+(0.25*sqrt(1-q))^2
//                             = 4q + (1-q)/16 = 0.0625 + 3.9375 q
//   w = rsqrt(0.0625+3.9375q) = 1/length  =>  nx = gx*w, ny = gy*w
//   4*nz = sqrt(1-q)*w ;  sqrt(1-q) ~= 1 - q/2 - q^2/8 (err <= q^3/16 <= 3.2e-5)
__device__ __forceinline__ void nrm(float gx, float gy,
                                    float& nx, float& ny, float& z4) {
    float q  = fmaf(gx, gx, gy * gy);
    float w  = rsqrtf(fmaf(3.9375f, q, 0.0625f));
    float su = fmaf(q, fmaf(q, -0.125f, -0.5f), 1.f);
    nx = gx * w;
    ny = gy * w;
    z4 = su * w;               // 4*nz ; 0.25 folded into final accumulation
}

// Accumulates |dnx|+|dny| into axy and |d(4nz)| into az.
__device__ __forceinline__ void contrib(
    float dpg, float dcg, float dng, float spg, float sng,
    float dpt, float dct, float dnt, float spt, float snt,
    float& axy, float& az) {
    float gxg = fmaf(2.f, dcg, dpg) + dng;
    float gyg = spg - sng;
    float gxt = fmaf(2.f, dct, dpt) + dnt;
    float gyt = spt - snt;
    float nxg, nyg, zg, nxt, nyt, zt;
    nrm(gxg, gyg, nxg, nyg, zg);
    nrm(gxt, gyt, nxt, nyt, zt);
    axy += fabsf(nxg - nxt) + fabsf(nyg - nyt);
    az  += fabsf(zg - zt);
}

__global__ void __launch_bounds__(NTHREADS, 8)
heightmap_loss_kernel(const float* __restrict__ gen, const float* __restrict__ tgt,
                      float* __restrict__ out, double inv_n) {
    const int b    = blockIdx.y;
    const int y0   = blockIdx.x * RPB;
    const int lane = threadIdx.x & 31;
    const int x0   = threadIdx.x * 4;
    const int xm   = max(x0 - 1, 0);
    const int xp   = min(x0 + 4, W_DIM - 1);
    const int nblocks = gridDim.x * gridDim.y;
    const int bid     = blockIdx.y * gridDim.x + blockIdx.x;

    const float* __restrict__ gimg = gen + (size_t)b * (H_DIM * W_DIM);
    const float* __restrict__ timg = tgt + (size_t)b * (H_DIM * W_DIM);

    // rolling 3-row window (prev, cur, next) per image
    DS gP, gC, gN, tP, tC, tN;
    {
        int ym = max(y0 - 1, 0);
        gP = row_ds(gimg + ym * W_DIM, x0, xm, xp);
        tP = row_ds(timg + ym * W_DIM, x0, xm, xp);
        gC = row_ds(gimg + y0 * W_DIM, x0, xm, xp);
        tC = row_ds(timg + y0 * W_DIM, x0, xm, xp);
    }

    float axy = 0.f, az = 0.f;
    #pragma unroll
    for (int yy = 0; yy < RPB; yy++) {
        int yn = min(y0 + yy + 1, H_DIM - 1);
        gN = row_ds(gimg + yn * W_DIM, x0, xm, xp);
        tN = row_ds(timg + yn * W_DIM, x0, xm, xp);

        contrib(gP.dx, gC.dx, gN.dx, gP.sx, gN.sx,
                tP.dx, tC.dx, tN.dx, tP.sx, tN.sx, axy, az);
        contrib(gP.dy, gC.dy, gN.dy, gP.sy, gN.sy,
                tP.dy, tC.dy, tN.dy, tP.sy, tN.sy, axy, az);
        contrib(gP.dz, gC.dz, gN.dz, gP.sz, gN.sz,
                tP.dz, tC.dz, tN.dz, tP.sz, tN.sz, axy, az);
        contrib(gP.dw, gC.dw, gN.dw, gP.sw, gN.sw,
                tP.dw, tC.dw, tN.dw, tP.sw, tN.sw, axy, az);

        gP = gC; gC = gN;
        tP = tC; tC = tN;
    }

    float acc = fmaf(0.25f, az, axy);

    // warp reduce
    #pragma unroll
    for (int o = 16; o > 0; o >>= 1)
        acc += __shfl_down_sync(0xffffffffu, acc, o);

    __shared__ float ws[NTHREADS / 32];
    __shared__ bool  isLast;
    if (lane == 0) ws[threadIdx.x >> 5] = acc;
    __syncthreads();
    if (threadIdx.x == 0) {
        g_part[bid] = ws[0] + ws[1] + ws[2] + ws[3];
        __threadfence();
        unsigned prev = atomicAdd(&g_ticket, 1u);
        isLast = (prev == (unsigned)(nblocks - 1));
    }
    __syncthreads();

    // Last block to finish performs the deterministic final reduction.
    if (isLast) {
        double s = 0.0;
        for (int i = threadIdx.x; i < nblocks; i += NTHREADS)
            s += (double)g_part[i];
        #pragma unroll
        for (int o = 16; o > 0; o >>= 1)
            s += __shfl_down_sync(0xffffffffu, s, o);
        __shared__ double ds[NTHREADS / 32];
        if (lane == 0) ds[threadIdx.x >> 5] = s;
        __syncthreads();
        if (threadIdx.x == 0) {
            double t = ds[0] + ds[1] + ds[2] + ds[3];
            out[0] = (float)(t * inv_n);
            g_ticket = 0u;   // restore invariant for graph replay
        }
    }
}

extern "C" void kernel_launch(void* const* d_in, const int* in_sizes, int n_in,
                              void* d_out, int out_size) {
    const float* gen = (const float*)d_in[0];
    const float* tgt = (const float*)d_in[1];
    float* out = (float*)d_out;

    const int total = in_sizes[0];              // B*1*H*W
    const int B = total / (H_DIM * W_DIM);

    dim3 grid(H_DIM / RPB, B);
    heightmap_loss_kernel<<<grid, NTHREADS>>>(gen, tgt, out,
                                              1.0 / (3.0 * (double)total));
}